// round 2
// baseline (speedup 1.0000x reference)
#include <cuda_runtime.h>

#define Bn 2
#define Cn 4
#define Kn 32
#define Hn 96
#define Wn 96
#define Dn 64
#define HWn (Hn*Wn)      /* 9216 */
#define Nn (Dn*Dn*Dn)    /* 262144 */

// Transposed heatmaps: [b][c][pixel][k]  (k contiguous -> coalesced warp gathers)
__device__ float g_hmT[(size_t)Bn*Cn*HWn*Kn];

__global__ void vt_transpose_kernel(const float* __restrict__ hm) {
    __shared__ float tile[32][33];
    const int bc = blockIdx.y;            // b*C + c  in [0,8)
    const int p0 = blockIdx.x * 32;       // pixel tile base
    const int tx = threadIdx.x, ty = threadIdx.y;
    // read: k = ty, pixel = p0 + tx  (coalesced over tx)
    tile[ty][tx] = hm[((size_t)bc*Kn + ty)*HWn + p0 + tx];
    __syncthreads();
    // write: pixel = p0 + ty, k = tx (coalesced over tx)
    g_hmT[((size_t)bc*HWn + p0 + ty)*Kn + tx] = tile[tx][ty];
}

__global__ void __launch_bounds__(256) vt_unproject_kernel(
    const float* __restrict__ P,       // (B,C,3,4)
    const float* __restrict__ coords,  // (B,D,D,D,3)
    const float* __restrict__ conf,    // (B,C,K)
    float* __restrict__ out)           // (B,K,D,D,D)
{
    const int warp = (blockIdx.x * blockDim.x + threadIdx.x) >> 5;
    const int lane = threadIdx.x & 31;
    const int gpb  = Nn / 32;                   // 8192 voxel-groups per batch
    const int b     = warp / gpb;
    const int nbase = (warp - b * gpb) * 32;

    // Per-k camera confidence weights, normalized over cameras (lane = k)
    float cw[Cn];
    float csum = 0.f;
    #pragma unroll
    for (int c = 0; c < Cn; ++c) {
        cw[c] = __ldg(conf + (b*Cn + c)*Kn + lane);
        csum += cw[c];
    }
    const float cinv = 1.0f / csum;
    #pragma unroll
    for (int c = 0; c < Cn; ++c) cw[c] *= cinv;

    // ---- Phase A: this lane's voxel = nbase + lane; project through 4 cams ----
    const float* cc = coords + (size_t)(b*Nn + nbase + lane) * 3;
    const float x = cc[0], y = cc[1], z = cc[2];
    const float SX = (float)(Wn - 1) / (float)Hn;   // ix = u*(W-1)/H
    const float SY = (float)(Hn - 1) / (float)Wn;   // iy = v*(H-1)/W
    float ixl[Cn], iyl[Cn];
    #pragma unroll
    for (int c = 0; c < Cn; ++c) {
        const float* Pm = P + (size_t)(b*Cn + c) * 12;
        float p0 = Pm[0]*x + Pm[1]*y + Pm[2] *z + Pm[3];
        float p1 = Pm[4]*x + Pm[5]*y + Pm[6] *z + Pm[7];
        float p2 = Pm[8]*x + Pm[9]*y + Pm[10]*z + Pm[11];
        if (p2 > 0.f) {
            ixl[c] = (p0 / p2) * SX;
            iyl[c] = (p1 / p2) * SY;
        } else {            // z<=0 -> invalid voxel/cam: force all corners OOB
            ixl[c] = -2e9f;
            iyl[c] = -2e9f;
        }
    }

    const float* planes = g_hmT + (size_t)(b*Cn) * HWn * Kn + lane;   // lane = k

    // ---- Phase B: lane = k; broadcast voxel data; coalesced corner gathers ----
    #pragma unroll 1
    for (int pass = 0; pass < 2; ++pass) {
        float acc[16];
        #pragma unroll
        for (int j = 0; j < 16; ++j) acc[j] = 0.f;

        #pragma unroll
        for (int j = 0; j < 16; ++j) {
            const int src = pass * 16 + j;
            #pragma unroll
            for (int c = 0; c < Cn; ++c) {
                const float ix = __shfl_sync(0xffffffffu, ixl[c], src);
                const float iy = __shfl_sync(0xffffffffu, iyl[c], src);
                const float x0f = floorf(ix), y0f = floorf(iy);
                const float wx1 = ix - x0f, wx0 = 1.f - wx1;
                const float wy1 = iy - y0f, wy0 = 1.f - wy1;
                // corner in-bounds (x1=x0+1, y1=y0+1); uniform across warp
                const bool x0in = (x0f >=  0.f) && (x0f <= (float)(Wn - 1));
                const bool x1in = (x0f >= -1.f) && (x0f <= (float)(Wn - 2));
                const bool y0in = (y0f >=  0.f) && (y0f <= (float)(Hn - 1));
                const bool y1in = (y0f >= -1.f) && (y0f <= (float)(Hn - 2));
                const int X0 = (int)x0f;
                const int Y0 = (int)y0f;
                const float* pl = planes + (size_t)c * HWn * Kn;
                float s = 0.f;
                if (y0in) {
                    const int rowb = (Y0*Wn + X0) * Kn;
                    if (x0in) s += wx0 * wy0 * __ldg(pl + rowb);
                    if (x1in) s += wx1 * wy0 * __ldg(pl + rowb + Kn);
                }
                if (y1in) {
                    const int rowb = ((Y0 + 1)*Wn + X0) * Kn;
                    if (x0in) s += wx0 * wy1 * __ldg(pl + rowb);
                    if (x1in) s += wx1 * wy1 * __ldg(pl + rowb + Kn);
                }
                acc[j] += cw[c] * s;
            }
        }
        // lane k owns 16 consecutive output voxels -> 4x float4 stores
        float4* o = (float4*)(out + (size_t)(b*Kn + lane)*Nn + nbase + pass*16);
        #pragma unroll
        for (int q = 0; q < 4; ++q)
            o[q] = make_float4(acc[4*q+0], acc[4*q+1], acc[4*q+2], acc[4*q+3]);
    }
}

extern "C" void kernel_launch(void* const* d_in, const int* in_sizes, int n_in,
                              void* d_out, int out_size) {
    const float* heatmaps = (const float*)d_in[0];   // (B,C,K,H,W)
    const float* projmat  = (const float*)d_in[1];   // (B,C,3,4)
    const float* coords   = (const float*)d_in[2];   // (B,D,D,D,3)
    const float* conf     = (const float*)d_in[3];   // (B,C,K)
    float* out = (float*)d_out;                      // (B,K,D,D,D)

    (void)in_sizes; (void)n_in; (void)out_size;

    dim3 tgrid(HWn / 32, Bn * Cn);
    dim3 tblk(32, 32);
    vt_transpose_kernel<<<tgrid, tblk>>>(heatmaps);

    const int total_warps = Bn * (Nn / 32);          // 16384
    const int threads = 256;
    const int blocks = total_warps * 32 / threads;   // 2048
    vt_unproject_kernel<<<blocks, threads>>>(projmat, coords, conf, out);
}

// round 6
// speedup vs baseline: 1.3548x; 1.3548x over previous
#include <cuda_runtime.h>

#define Bn 2
#define Cn 4
#define Kn 32
#define Hn 96
#define Wn 96
#define Dn 64
#define HWn (Hn*Wn)      /* 9216 */
#define Nn (Dn*Dn*Dn)    /* 262144 */

// Transposed heatmaps: [b][c][pixel][k]  (k contiguous -> coalesced warp gathers)
__device__ float g_hmT[(size_t)Bn*Cn*HWn*Kn];

__global__ void vt_transpose_kernel(const float* __restrict__ hm) {
    __shared__ float tile[32][33];
    const int bc = blockIdx.y;            // b*C + c  in [0,8)
    const int p0 = blockIdx.x * 32;       // pixel tile base
    const int tx = threadIdx.x, ty = threadIdx.y;
    tile[ty][tx] = hm[((size_t)bc*Kn + ty)*HWn + p0 + tx];
    __syncthreads();
    g_hmT[((size_t)bc*HWn + p0 + ty)*Kn + tx] = tile[tx][ty];
}

__global__ void __launch_bounds__(256) vt_unproject_kernel(
    const float* __restrict__ P,       // (B,C,3,4)
    const float* __restrict__ coords,  // (B,D,D,D,3)
    const float* __restrict__ conf,    // (B,C,K)
    float* __restrict__ out)           // (B,K,D,D,D)
{
    // Per-warp precomputed sample table: [cam][half(x-col)][voxel] ->
    //   half 0: {bits(idx_x0y0), w00, bits(idx_x0y1), w01}
    //   half 1: {bits(idx_x1y0), w10, bits(idx_x1y1), w11}
    __shared__ float4 sm[8][Cn][2][32];

    const int wib  = threadIdx.x >> 5;          // warp in block
    const int lane = threadIdx.x & 31;
    const int warp = blockIdx.x * 8 + wib;
    const int gpb  = Nn / 32;                   // 8192 voxel-groups per batch
    const int b     = warp / gpb;
    const int nbase = (warp - b * gpb) * 32;
    const int kpair = lane & 15;                // k in {2*kpair, 2*kpair+1}
    const int half  = lane >> 4;                // x-column (x0 vs x1)

    // Per-k-pair camera confidence weights, normalized over cameras
    float2 cw[Cn];
    float sx = 0.f, sy = 0.f;
    #pragma unroll
    for (int c = 0; c < Cn; ++c) {
        cw[c] = *(const float2*)(conf + (b*Cn + c)*Kn + 2*kpair);
        sx += cw[c].x; sy += cw[c].y;
    }
    const float isx = 1.0f / sx, isy = 1.0f / sy;
    #pragma unroll
    for (int c = 0; c < Cn; ++c) { cw[c].x *= isx; cw[c].y *= isy; }

    // ---- Phase A: lane = voxel; project through 4 cams, build sample table ----
    const float* cc = coords + (size_t)(b*Nn + nbase + lane) * 3;
    const float x = cc[0], y = cc[1], z = cc[2];
    const float SX = (float)(Wn - 1) / (float)Hn;   // ix = u*(W-1)/H
    const float SY = (float)(Hn - 1) / (float)Wn;   // iy = v*(H-1)/W
    unsigned livemask[Cn];

    #pragma unroll
    for (int c = 0; c < Cn; ++c) {
        const float* Pm = P + (size_t)(b*Cn + c) * 12;
        float p0 = Pm[0]*x + Pm[1]*y + Pm[2] *z + Pm[3];
        float p1 = Pm[4]*x + Pm[5]*y + Pm[6] *z + Pm[7];
        float p2 = Pm[8]*x + Pm[9]*y + Pm[10]*z + Pm[11];
        float ix, iy;
        if (p2 > 0.f) { ix = (p0 / p2) * SX; iy = (p1 / p2) * SY; }
        else          { ix = -2e9f;          iy = -2e9f; }

        const float x0f = floorf(ix), y0f = floorf(iy);
        const float wx1 = ix - x0f, wx0 = 1.f - wx1;
        const float wy1 = iy - y0f, wy0 = 1.f - wy1;
        const int X0 = (int)x0f, Y0 = (int)y0f;
        const int X1 = X0 + 1,   Y1 = Y0 + 1;

        const bool x0in = (X0 >= 0) & (X0 < Wn);
        const bool x1in = (X1 >= 0) & (X1 < Wn);
        const bool y0in = (Y0 >= 0) & (Y0 < Hn);
        const bool y1in = (Y1 >= 0) & (Y1 < Hn);
        const int x0c = min(max(X0, 0), Wn-1), x1c = min(max(X1, 0), Wn-1);
        const int y0c = min(max(Y0, 0), Hn-1), y1c = min(max(Y1, 0), Hn-1);

        // byte offsets into [pixel][k] plane (K floats = 128B per pixel)
        const int i00 = (y0c*Wn + x0c) * (Kn*4);
        const int i10 = (y0c*Wn + x1c) * (Kn*4);
        const int i01 = (y1c*Wn + x0c) * (Kn*4);
        const int i11 = (y1c*Wn + x1c) * (Kn*4);

        const float w00 = (x0in & y0in) ? wx0*wy0 : 0.f;
        const float w10 = (x1in & y0in) ? wx1*wy0 : 0.f;
        const float w01 = (x0in & y1in) ? wx0*wy1 : 0.f;
        const float w11 = (x1in & y1in) ? wx1*wy1 : 0.f;

        sm[wib][c][0][lane] = make_float4(__int_as_float(i00), w00,
                                          __int_as_float(i01), w01);
        sm[wib][c][1][lane] = make_float4(__int_as_float(i10), w10,
                                          __int_as_float(i11), w11);
        const bool live = (w00 + w10 + w01 + w11) > 0.f;
        livemask[c] = __ballot_sync(0xffffffffu, live);
    }
    __syncwarp();

    // Gather base pointers: lane's k-pair within each camera plane
    const char* basep[Cn];
    #pragma unroll
    for (int c = 0; c < Cn; ++c)
        basep[c] = (const char*)(g_hmT + ((size_t)(b*Cn + c) * HWn) * Kn + 2*kpair);

    // smem read base for this lane's half: sm[wib][c][half][j] = smr[c*64 + j]
    const float4* smr = &sm[wib][0][half][0];

    // ---- Phase B: lane = (half, kpair); 4 passes of 8 voxels ----
    #pragma unroll 1
    for (int pass = 0; pass < 4; ++pass) {
        float2 acc[8];
        #pragma unroll
        for (int jj = 0; jj < 8; ++jj) acc[jj] = make_float2(0.f, 0.f);

        #pragma unroll
        for (int jj = 0; jj < 8; ++jj) {
            const int j = pass*8 + jj;
            #pragma unroll
            for (int c = 0; c < Cn; ++c) {
                if (!((livemask[c] >> j) & 1u)) continue;   // warp-uniform skip
                const float4 e = smr[c*64 + j];
                const float2 v0 = *(const float2*)(basep[c] + __float_as_int(e.x));
                const float2 v1 = *(const float2*)(basep[c] + __float_as_int(e.z));
                const float px = e.y*v0.x + e.w*v1.x;   // this half's 2 corners
                const float py = e.y*v0.y + e.w*v1.y;
                acc[jj].x = fmaf(cw[c].x, px, acc[jj].x);
                acc[jj].y = fmaf(cw[c].y, py, acc[jj].y);
            }
        }

        // combine the two x-columns (halves): bfly over lane bit 4
        float r[8];
        #pragma unroll
        for (int jj = 0; jj < 8; ++jj) {
            const float ox = __shfl_xor_sync(0xffffffffu, acc[jj].x, 16);
            const float oy = __shfl_xor_sync(0xffffffffu, acc[jj].y, 16);
            const float fx = acc[jj].x + ox;
            const float fy = acc[jj].y + oy;
            r[jj] = half ? fy : fx;      // half 0 stores k=2*kpair, half 1 stores k=2*kpair+1
        }

        float* op = out + ((size_t)(b*Kn + 2*kpair + half))*Nn + nbase + pass*8;
        ((float4*)op)[0] = make_float4(r[0], r[1], r[2], r[3]);
        ((float4*)op)[1] = make_float4(r[4], r[5], r[6], r[7]);
    }
}

extern "C" void kernel_launch(void* const* d_in, const int* in_sizes, int n_in,
                              void* d_out, int out_size) {
    const float* heatmaps = (const float*)d_in[0];   // (B,C,K,H,W)
    const float* projmat  = (const float*)d_in[1];   // (B,C,3,4)
    const float* coords   = (const float*)d_in[2];   // (B,D,D,D,3)
    const float* conf     = (const float*)d_in[3];   // (B,C,K)
    float* out = (float*)d_out;                      // (B,K,D,D,D)

    (void)in_sizes; (void)n_in; (void)out_size;

    dim3 tgrid(HWn / 32, Bn * Cn);
    dim3 tblk(32, 32);
    vt_transpose_kernel<<<tgrid, tblk>>>(heatmaps);

    const int total_warps = Bn * (Nn / 32);          // 16384
    const int blocks = total_warps / 8;              // 2048 blocks of 8 warps
    vt_unproject_kernel<<<blocks, 256>>>(projmat, coords, conf, out);
}